// round 8
// baseline (speedup 1.0000x reference)
#include <cuda_runtime.h>

typedef unsigned long long u64;
typedef unsigned u32;
#define DI __device__ __forceinline__

// gathered weights: [0:16) W1 | [16:24) b1 | [24:56) W2 | [56:60) b2 | [60:68) W3
__device__   float gAll[68];
__constant__ float cAll[68];

// ---------- packed f32x2 helpers (PTX-only on sm_103a) ----------
DI u64 pack2(float lo, float hi) {
    u64 r;
    asm("mov.b64 %0, {%1, %2};"
        : "=l"(r) : "r"(__float_as_uint(lo)), "r"(__float_as_uint(hi)));
    return r;
}
DI void unpack2(u64 v, u32& lo, u32& hi) {
    asm("mov.b64 {%0, %1}, %2;" : "=r"(lo), "=r"(hi) : "l"(v));
}
DI u64 fma2(u64 a, u64 b, u64 c) {
    u64 d;
    asm("fma.rn.f32x2 %0, %1, %2, %3;" : "=l"(d) : "l"(a), "l"(b), "l"(c));
    return d;
}
DI u64 add2(u64 a, u64 b) {
    u64 d;
    asm("add.rn.f32x2 %0, %1, %2;" : "=l"(d) : "l"(a), "l"(b));
    return d;
}
DI u32 prmt(u32 a, u32 b, u32 sel) {
    u32 d;
    asm("prmt.b32 %0, %1, %2, %3;" : "=r"(d) : "r"(a), "r"(b), "r"(sel));
    return d;
}
// sign bytes of 4 floats -> [sA,sB,sC,sD] (0xFF where negative)
DI u32 sgn4(u32 a, u32 b, u32 c, u32 d) {
    const u32 ab = prmt(a, b, 0xFBFB);
    const u32 cd = prmt(c, d, 0xFBFB);
    return prmt(ab, cd, 0x5410);
}
DI u32 dp4a(u32 a, u32 b, u32 c) {
    u32 d;
    asm("dp4a.u32.u32 %0, %1, %2, %3;" : "=r"(d) : "r"(a), "r"(b), "r"(c));
    return d;
}

// weight source: true -> constant bank (uniform datapath), false -> global
template <bool C>
struct Src {
    const float* g;
    DI float w(int i) const { return C ? cAll[i] : __ldg(&g[i]); }
    DI u64  wp(int i) const { const float v = w(i); return pack2(v, v); }
};

// One position: given z1 sign offsets (d1a = m1lo*8, d1b = m1hi*8) and (x,y),
// fetch affine layer-2 coeffs, get m2, combine split force tables.
DI u64 finish(u32 d1a, u32 d1b, float x, float y,
              const char* __restrict__ ax, const char* __restrict__ ay,
              const char* __restrict__ cc,
              const char* __restrict__ tl, const char* __restrict__ th) {
    const u32 off = (d1a << 1) + (d1b << 5);        // m1 * 16 bytes
    const float4 A = *(const float4*)(ax + off);
    const float4 B = *(const float4*)(ay + off);
    const float4 Cc = *(const float4*)(cc + off);

    const float z0 = fmaf(A.x, x, fmaf(B.x, y, Cc.x));
    const float z1 = fmaf(A.y, x, fmaf(B.y, y, Cc.y));
    const float z2 = fmaf(A.z, x, fmaf(B.z, y, Cc.z));
    const float z3 = fmaf(A.w, x, fmaf(B.w, y, Cc.w));

    const u32 K2 = 0x08040201u, ONES = 0x01010101u;
    const u32 s = sgn4(__float_as_uint(z0), __float_as_uint(z1),
                       __float_as_uint(z2), __float_as_uint(z3));
    const u32 m2s = dp4a(s & K2, ONES, 0) << 7;     // m2 * 128 bytes

    return add2(*(const u64*)(tl + (d1a + m2s)),
                *(const u64*)(th + (d1b + m2s)));
}

// one-warp gather: 5 arrays -> contiguous gAll
__global__ void gather_weights(const float* __restrict__ W1,
                               const float* __restrict__ b1,
                               const float* __restrict__ W2,
                               const float* __restrict__ b2,
                               const float* __restrict__ W3) {
    const int t = threadIdx.x;
    if (t < 16)       gAll[t] = W1[t];
    else if (t < 24)  gAll[t] = b1[t - 16];
    else if (t < 56)  gAll[t] = W2[t - 24];
    else if (t < 60)  gAll[t] = b2[t - 56];
    else if (t < 68)  gAll[t] = W3[t - 60];
}

template <bool C>
__global__ void __launch_bounds__(128, 8) toy_force_kernel(
    const float4* __restrict__ pos,
    const float*  __restrict__ gw,
    float4*       __restrict__ out,
    int npairs)
{
    __shared__ float  u_s[16][8];  // u(m2)_i = sum_{j act} (-v3_j) W2[j][i]
    __shared__ u64    tlo[256];    // force of m1[0:4] given m2
    __shared__ u64    thi[256];    // force of m1[4:8] given m2
    __shared__ float4 sAx[256];    // layer2 affine coeffs vs m1: z2_j partial x
    __shared__ float4 sAy[256];    //   ... partial y
    __shared__ float4 sC[256];     //   ... constant (incl b2)

    Src<C> S{gw};
    const int tid = threadIdx.x;

    // ---- u table: one (m2, i) per thread ----
    {
        const int i = tid & 7, m = tid >> 3;
        float s = 0.f;
#pragma unroll
        for (int j = 0; j < 4; j++) {
            const float v3n = -(S.w(60 + j) + S.w(64 + j));   // fold -grad
            if (!((m >> j) & 1)) s += v3n * S.w(24 + 8 * j + i);
        }
        u_s[m][i] = s;
    }
    __syncthreads();

    // ---- split force tables: 512 entries ----
    for (int e = tid; e < 512; e += blockDim.x) {
        const bool hi = e >= 256;
        const int ent = e & 255;
        const int m1h = ent & 15, m2 = ent >> 4;
        const int base = hi ? 4 : 0;
        float fx = 0.f, fy = 0.f;
#pragma unroll
        for (int k = 0; k < 4; k++) {
            const int i = base + k;
            const float msk = ((m1h >> k) & 1) ? 0.f : 1.f;
            const float ui = msk * u_s[m2][i];
            fx = fmaf(ui, S.w(2 * i), fx);
            fy = fmaf(ui, S.w(2 * i + 1), fy);
        }
        (hi ? thi : tlo)[ent] = pack2(fx, fy);
    }

    // ---- layer-2 affine coeff tables vs m1 (bit set = neuron inactive) ----
    for (int e = tid; e < 256; e += blockDim.x) {
        float axv[4], ayv[4], cv[4];
#pragma unroll
        for (int j = 0; j < 4; j++) {
            axv[j] = 0.f; ayv[j] = 0.f; cv[j] = S.w(56 + j);
        }
#pragma unroll
        for (int i = 0; i < 8; i++) {
            if (!((e >> i) & 1)) {
                const float wx = S.w(2 * i), wy = S.w(2 * i + 1), bb = S.w(16 + i);
#pragma unroll
                for (int j = 0; j < 4; j++) {
                    const float w2 = S.w(24 + 8 * j + i);
                    axv[j] = fmaf(w2, wx, axv[j]);
                    ayv[j] = fmaf(w2, wy, ayv[j]);
                    cv[j]  = fmaf(w2, bb, cv[j]);
                }
            }
        }
        sAx[e] = make_float4(axv[0], axv[1], axv[2], axv[3]);
        sAy[e] = make_float4(ayv[0], ayv[1], ayv[2], ayv[3]);
        sC[e]  = make_float4(cv[0],  cv[1],  cv[2],  cv[3]);
    }
    __syncthreads();

    const char* tl = (const char*)tlo;
    const char* th = (const char*)thi;
    const char* ax = (const char*)sAx;
    const char* ay = (const char*)sAy;
    const char* cc = (const char*)sC;
    const int stride = gridDim.x * blockDim.x;

    const u32 K1 = 0x40201008u, ONES = 0x01010101u;

    // ---- grid-stride, ILP=2, rotating double prefetch ----
    int ka = blockIdx.x * blockDim.x + tid;
    if (ka >= npairs) return;
    int kb = ka + stride;
    bool hb = kb < npairs;

    float4 pa = pos[ka];
    float4 pb = hb ? pos[kb] : pa;

    for (;;) {
        const int kan = ka + 2 * stride;
        const int kbn = kb + 2 * stride;
        const bool han = kan < npairs;
        const bool hbn = hb && (kbn < npairs);
        float4 na, nb;
        if (han) na = pos[kan];
        if (hbn) nb = pos[kbn];

        // ---- eval A ----
        {
            const u64 PX = pack2(pa.x, pa.z);
            const u64 PY = pack2(pa.y, pa.w);
            u32 zl[8], zh[8];
#pragma unroll
            for (int i = 0; i < 8; i++) {
                const u64 z = fma2(S.wp(2 * i), PX,
                                   fma2(S.wp(2 * i + 1), PY, S.wp(16 + i)));
                unpack2(z, zl[i], zh[i]);
            }
            const u32 d1a0 = dp4a(sgn4(zl[0], zl[1], zl[2], zl[3]) & K1, ONES, 0);
            const u32 d1b0 = dp4a(sgn4(zl[4], zl[5], zl[6], zl[7]) & K1, ONES, 0);
            const u32 d1a1 = dp4a(sgn4(zh[0], zh[1], zh[2], zh[3]) & K1, ONES, 0);
            const u32 d1b1 = dp4a(sgn4(zh[4], zh[5], zh[6], zh[7]) & K1, ONES, 0);
            const u64 F0 = finish(d1a0, d1b0, pa.x, pa.y, ax, ay, cc, tl, th);
            const u64 F1 = finish(d1a1, d1b1, pa.z, pa.w, ax, ay, cc, tl, th);
            *(ulonglong2*)&out[ka] = make_ulonglong2(F0, F1);
        }
        // ---- eval B ----
        if (hb) {
            const u64 PX = pack2(pb.x, pb.z);
            const u64 PY = pack2(pb.y, pb.w);
            u32 zl[8], zh[8];
#pragma unroll
            for (int i = 0; i < 8; i++) {
                const u64 z = fma2(S.wp(2 * i), PX,
                                   fma2(S.wp(2 * i + 1), PY, S.wp(16 + i)));
                unpack2(z, zl[i], zh[i]);
            }
            const u32 d1a0 = dp4a(sgn4(zl[0], zl[1], zl[2], zl[3]) & K1, ONES, 0);
            const u32 d1b0 = dp4a(sgn4(zl[4], zl[5], zl[6], zl[7]) & K1, ONES, 0);
            const u32 d1a1 = dp4a(sgn4(zh[0], zh[1], zh[2], zh[3]) & K1, ONES, 0);
            const u32 d1b1 = dp4a(sgn4(zh[4], zh[5], zh[6], zh[7]) & K1, ONES, 0);
            const u64 G0 = finish(d1a0, d1b0, pb.x, pb.y, ax, ay, cc, tl, th);
            const u64 G1 = finish(d1a1, d1b1, pb.z, pb.w, ax, ay, cc, tl, th);
            *(ulonglong2*)&out[kb] = make_ulonglong2(G0, G1);
        }

        if (!han) break;
        pa = na;
        pb = hbn ? nb : na;
        ka = kan;
        kb = kbn;
        hb = hbn;
    }
}

extern "C" void kernel_launch(void* const* d_in, const int* in_sizes, int n_in,
                              void* d_out, int out_size) {
    const float* pos = (const float*)d_in[0];
    const float* W1  = (const float*)d_in[1];
    const float* b1  = (const float*)d_in[2];
    const float* W2  = (const float*)d_in[3];
    const float* b2  = (const float*)d_in[4];
    const float* W3  = (const float*)d_in[5];
    float* out = (float*)d_out;

    const int npairs = in_sizes[0] / 4;   // one float4 = 2 positions

    gather_weights<<<1, 68>>>(W1, b1, W2, b2, W3);

    void* gptr = nullptr;
    bool ok = cudaGetSymbolAddress(&gptr, gAll) == cudaSuccess;
    if (ok)
        ok = cudaMemcpyToSymbolAsync(cAll, gptr, 68 * sizeof(float), 0,
                                     cudaMemcpyDeviceToDevice, 0) == cudaSuccess;

    const int threads = 128;
    const int blocks  = 1184;             // 148 SMs x 8 CTAs
    if (ok) {
        toy_force_kernel<true><<<blocks, threads>>>(
            (const float4*)pos, (const float*)gptr, (float4*)out, npairs);
    } else {
        toy_force_kernel<false><<<blocks, threads>>>(
            (const float4*)pos, (const float*)gptr, (float4*)out, npairs);
    }
}

// round 9
// speedup vs baseline: 1.0010x; 1.0010x over previous
#include <cuda_runtime.h>

typedef unsigned long long u64;
typedef unsigned u32;
#define DI __device__ __forceinline__

// one combined staging struct -> single memcpy node
// all: [0:16) W1 | [16:24) b1 | [24:56) W2 | [56:60) b2 | [60:68) W3
// pk (u64, value duplicated in both lanes):
//   [0..7] w1x | [8..15] w1y | [16..23] b1 | [24..55] W2 | [56..59] b2
struct CBuf {
    float all[68];
    u64   pk[60];
};
__device__   CBuf gBuf;
__constant__ CBuf cBuf;

// ---------- packed f32x2 helpers (PTX-only on sm_103a) ----------
DI u64 pack2(float lo, float hi) {
    u64 r;
    asm("mov.b64 %0, {%1, %2};"
        : "=l"(r) : "r"(__float_as_uint(lo)), "r"(__float_as_uint(hi)));
    return r;
}
DI void unpack2(u64 v, u32& lo, u32& hi) {
    asm("mov.b64 {%0, %1}, %2;" : "=r"(lo), "=r"(hi) : "l"(v));
}
DI u64 fma2(u64 a, u64 b, u64 c) {
    u64 d;
    asm("fma.rn.f32x2 %0, %1, %2, %3;" : "=l"(d) : "l"(a), "l"(b), "l"(c));
    return d;
}
DI u64 add2(u64 a, u64 b) {
    u64 d;
    asm("add.rn.f32x2 %0, %1, %2;" : "=l"(d) : "l"(a), "l"(b));
    return d;
}
DI u32 prmt(u32 a, u32 b, u32 sel) {
    u32 d;
    asm("prmt.b32 %0, %1, %2, %3;" : "=r"(d) : "r"(a), "r"(b), "r"(sel));
    return d;
}
// sign bytes of 4 floats -> [sA,sB,sC,sD] (0xFF where negative)
DI u32 sgn4(u32 a, u32 b, u32 c, u32 d) {
    const u32 ab = prmt(a, b, 0xFBFB);
    const u32 cd = prmt(c, d, 0xFBFB);
    return prmt(ab, cd, 0x5410);
}
DI u32 dp4a(u32 a, u32 b, u32 c) {
    u32 d;
    asm("dp4a.u32.u32 %0, %1, %2, %3;" : "=r"(d) : "r"(a), "r"(b), "r"(c));
    return d;
}

// weight source: true -> constant bank, false -> global staging buffer
template <bool C>
struct Src {
    DI float w(int i) const { return C ? cBuf.all[i] : gBuf.all[i]; }
    DI u64  wp(int i) const { return C ? cBuf.pk[i]  : gBuf.pk[i];  }
};

// one-warp gather: 5 arrays -> gBuf (scalar + pre-duplicated u64 views)
__global__ void gather_weights(const float* __restrict__ W1,
                               const float* __restrict__ b1,
                               const float* __restrict__ W2,
                               const float* __restrict__ b2,
                               const float* __restrict__ W3) {
    const int t = threadIdx.x;
    if (t < 68) {
        float v;
        if (t < 16)       v = W1[t];
        else if (t < 24)  v = b1[t - 16];
        else if (t < 56)  v = W2[t - 24];
        else if (t < 60)  v = b2[t - 56];
        else              v = W3[t - 60];
        gBuf.all[t] = v;
    }
    if (t < 60) {
        float v;
        if (t < 8)        v = W1[2 * t];              // w1x
        else if (t < 16)  v = W1[2 * (t - 8) + 1];    // w1y
        else if (t < 24)  v = b1[t - 16];             // b1
        else if (t < 56)  v = W2[t - 24];             // W2
        else              v = b2[t - 56];             // b2
        gBuf.pk[t] = pack2(v, v);
    }
}

template <bool C>
__global__ void __launch_bounds__(256, 4) toy_force_kernel(
    const float4* __restrict__ pos,
    float4*       __restrict__ out,
    int npairs)
{
    __shared__ float u_s[16][8];   // u(m2)_i = sum_{j act} (-v3_j) W2[j][i]
    __shared__ u64 tlo[256];       // force of m1[0:4] given m2
    __shared__ u64 thi[256];       // force of m1[4:8] given m2

    Src<C> S;
    const int tid = threadIdx.x;

    // ---- u table: one (m2, i) per thread (first 128 threads) ----
    if (tid < 128) {
        const int i = tid & 7, m = tid >> 3;
        float s = 0.f;
#pragma unroll
        for (int j = 0; j < 4; j++) {
            const float v3n = -(S.w(60 + j) + S.w(64 + j));   // fold -grad
            if (!((m >> j) & 1)) s += v3n * S.w(24 + 8 * j + i);
        }
        u_s[m][i] = s;
    }
    __syncthreads();

    // ---- split force tables: 512 entries ----
    for (int e = tid; e < 512; e += blockDim.x) {
        const bool hi = e >= 256;
        const int ent = e & 255;
        const int m1h = ent & 15, m2 = ent >> 4;
        const int base = hi ? 4 : 0;
        float fx = 0.f, fy = 0.f;
#pragma unroll
        for (int k = 0; k < 4; k++) {
            const int i = base + k;
            const float msk = ((m1h >> k) & 1) ? 0.f : 1.f;
            const float ui = msk * u_s[m2][i];
            fx = fmaf(ui, S.w(2 * i), fx);
            fy = fmaf(ui, S.w(2 * i + 1), fy);
        }
        (hi ? thi : tlo)[ent] = pack2(fx, fy);
    }
    __syncthreads();

    const char* tl = (const char*)tlo;
    const char* th = (const char*)thi;
    const int stride = gridDim.x * blockDim.x;

    const u32 K1 = 0x40201008u;   // byte weights 8,16,32,64 (m1 bits * 8B)
    const u32 K2 = 0x08040201u;
    const u32 ONES = 0x01010101u;

    // ---- grid-stride, ILP=2, rotating double prefetch ----
    int ka = blockIdx.x * blockDim.x + tid;
    if (ka >= npairs) return;
    int kb = ka + stride;
    bool hb = kb < npairs;

    float4 pa = pos[ka];
    float4 pb = hb ? pos[kb] : pa;

    for (;;) {
        const int kan = ka + 2 * stride;
        const int kbn = kb + 2 * stride;
        const bool han = kan < npairs;
        const bool hbn = hb && (kbn < npairs);
        float4 na, nb;
        if (han) na = pos[kan];
        if (hbn) nb = pos[kbn];

        // ---- eval A ----
        {
            const u64 PX = pack2(pa.x, pa.z);
            const u64 PY = pack2(pa.y, pa.w);
            u32 zl[8], zh[8];
            u64 h1[8];
#pragma unroll
            for (int i = 0; i < 8; i++) {
                const u64 z = fma2(S.wp(i), PX,
                                   fma2(S.wp(8 + i), PY, S.wp(16 + i)));
                unpack2(z, zl[i], zh[i]);
                h1[i] = pack2(fmaxf(__uint_as_float(zl[i]), 0.f),
                              fmaxf(__uint_as_float(zh[i]), 0.f));
            }
            u32 al[4], ah[4];
#pragma unroll
            for (int j = 0; j < 4; j++) {
                u64 acc = S.wp(56 + j);
#pragma unroll
                for (int i = 0; i < 8; i++)
                    acc = fma2(S.wp(24 + 8 * j + i), h1[i], acc);
                unpack2(acc, al[j], ah[j]);
            }
            const u32 d1a0 = dp4a(sgn4(zl[0], zl[1], zl[2], zl[3]) & K1, ONES, 0);
            const u32 d1b0 = dp4a(sgn4(zl[4], zl[5], zl[6], zl[7]) & K1, ONES, 0);
            const u32 m2s0 = dp4a(sgn4(al[0], al[1], al[2], al[3]) & K2, ONES, 0) << 7;
            const u32 d1a1 = dp4a(sgn4(zh[0], zh[1], zh[2], zh[3]) & K1, ONES, 0);
            const u32 d1b1 = dp4a(sgn4(zh[4], zh[5], zh[6], zh[7]) & K1, ONES, 0);
            const u32 m2s1 = dp4a(sgn4(ah[0], ah[1], ah[2], ah[3]) & K2, ONES, 0) << 7;
            const u64 F0 = add2(*(const u64*)(tl + (d1a0 + m2s0)),
                                *(const u64*)(th + (d1b0 + m2s0)));
            const u64 F1 = add2(*(const u64*)(tl + (d1a1 + m2s1)),
                                *(const u64*)(th + (d1b1 + m2s1)));
            *(ulonglong2*)&out[ka] = make_ulonglong2(F0, F1);
        }
        // ---- eval B ----
        if (hb) {
            const u64 PX = pack2(pb.x, pb.z);
            const u64 PY = pack2(pb.y, pb.w);
            u32 zl[8], zh[8];
            u64 h1[8];
#pragma unroll
            for (int i = 0; i < 8; i++) {
                const u64 z = fma2(S.wp(i), PX,
                                   fma2(S.wp(8 + i), PY, S.wp(16 + i)));
                unpack2(z, zl[i], zh[i]);
                h1[i] = pack2(fmaxf(__uint_as_float(zl[i]), 0.f),
                              fmaxf(__uint_as_float(zh[i]), 0.f));
            }
            u32 al[4], ah[4];
#pragma unroll
            for (int j = 0; j < 4; j++) {
                u64 acc = S.wp(56 + j);
#pragma unroll
                for (int i = 0; i < 8; i++)
                    acc = fma2(S.wp(24 + 8 * j + i), h1[i], acc);
                unpack2(acc, al[j], ah[j]);
            }
            const u32 d1a0 = dp4a(sgn4(zl[0], zl[1], zl[2], zl[3]) & K1, ONES, 0);
            const u32 d1b0 = dp4a(sgn4(zl[4], zl[5], zl[6], zl[7]) & K1, ONES, 0);
            const u32 m2s0 = dp4a(sgn4(al[0], al[1], al[2], al[3]) & K2, ONES, 0) << 7;
            const u32 d1a1 = dp4a(sgn4(zh[0], zh[1], zh[2], zh[3]) & K1, ONES, 0);
            const u32 d1b1 = dp4a(sgn4(zh[4], zh[5], zh[6], zh[7]) & K1, ONES, 0);
            const u32 m2s1 = dp4a(sgn4(ah[0], ah[1], ah[2], ah[3]) & K2, ONES, 0) << 7;
            const u64 G0 = add2(*(const u64*)(tl + (d1a0 + m2s0)),
                                *(const u64*)(th + (d1b0 + m2s0)));
            const u64 G1 = add2(*(const u64*)(tl + (d1a1 + m2s1)),
                                *(const u64*)(th + (d1b1 + m2s1)));
            *(ulonglong2*)&out[kb] = make_ulonglong2(G0, G1);
        }

        if (!han) break;
        pa = na;
        pb = hbn ? nb : na;
        ka = kan;
        kb = kbn;
        hb = hbn;
    }
}

extern "C" void kernel_launch(void* const* d_in, const int* in_sizes, int n_in,
                              void* d_out, int out_size) {
    const float* pos = (const float*)d_in[0];
    const float* W1  = (const float*)d_in[1];
    const float* b1  = (const float*)d_in[2];
    const float* W2  = (const float*)d_in[3];
    const float* b2  = (const float*)d_in[4];
    const float* W3  = (const float*)d_in[5];
    float* out = (float*)d_out;

    const int npairs = in_sizes[0] / 4;   // one float4 = 2 positions

    gather_weights<<<1, 128>>>(W1, b1, W2, b2, W3);

    void* gptr = nullptr;
    bool ok = cudaGetSymbolAddress(&gptr, gBuf) == cudaSuccess;
    if (ok)
        ok = cudaMemcpyToSymbolAsync(cBuf, gptr, sizeof(CBuf), 0,
                                     cudaMemcpyDeviceToDevice, 0) == cudaSuccess;

    const int threads = 256;
    const int blocks  = 592;              // 148 SMs x 4 CTAs x 256 thr
    if (ok) {
        toy_force_kernel<true><<<blocks, threads>>>(
            (const float4*)pos, (float4*)out, npairs);
    } else {
        toy_force_kernel<false><<<blocks, threads>>>(
            (const float4*)pos, (float4*)out, npairs);
    }
}

// round 10
// speedup vs baseline: 1.4677x; 1.4662x over previous
#include <cuda_runtime.h>

typedef unsigned long long u64;
typedef unsigned u32;
#define DI __device__ __forceinline__

// single staging struct -> one memcpy node
// all: [0:16) W1 | [16:24) b1 | [24:56) W2 | [56:60) b2 | [60:68) W3
// pk2: compact packed weights (30 u64):
//  [0..3]  W1px[k] = (W1[2k][0],   W1[2k+1][0])
//  [4..7]  W1py[k] = (W1[2k][1],   W1[2k+1][1])
//  [8..11] B1p[k]  = (b1[2k],      b1[2k+1])
//  [12..27] W2p[a][i] = (W2[2a][i], W2[2a+1][i])   (a in {0,1}, i in 0..7)
//  [28..29] B2p[a] = (b2[2a], b2[2a+1])
struct CBuf {
    float all[68];
    u64   pk2[30];
};
__device__   CBuf gBuf;
__constant__ CBuf cBuf;

// ---------- packed f32x2 helpers (PTX-only on sm_103a) ----------
DI u64 pack2(float lo, float hi) {
    u64 r;
    asm("mov.b64 %0, {%1, %2};"
        : "=l"(r) : "r"(__float_as_uint(lo)), "r"(__float_as_uint(hi)));
    return r;
}
DI u64 dup2(float v) {
    u64 r;
    asm("mov.b64 %0, {%1, %1};" : "=l"(r) : "r"(__float_as_uint(v)));
    return r;
}
DI void unpack2(u64 v, u32& lo, u32& hi) {
    asm("mov.b64 {%0, %1}, %2;" : "=r"(lo), "=r"(hi) : "l"(v));
}
DI u64 fma2(u64 a, u64 b, u64 c) {
    u64 d;
    asm("fma.rn.f32x2 %0, %1, %2, %3;" : "=l"(d) : "l"(a), "l"(b), "l"(c));
    return d;
}
DI u64 mul2(u64 a, u64 b) {
    u64 d;
    asm("mul.rn.f32x2 %0, %1, %2;" : "=l"(d) : "l"(a), "l"(b));
    return d;
}
DI u64 add2(u64 a, u64 b) {
    u64 d;
    asm("add.rn.f32x2 %0, %1, %2;" : "=l"(d) : "l"(a), "l"(b));
    return d;
}
DI u32 prmt(u32 a, u32 b, u32 sel) {
    u32 d;
    asm("prmt.b32 %0, %1, %2, %3;" : "=r"(d) : "r"(a), "r"(b), "r"(sel));
    return d;
}
// sign bytes of 4 floats -> [sA,sB,sC,sD] (0xFF where negative)
DI u32 sgn4(u32 a, u32 b, u32 c, u32 d) {
    const u32 ab = prmt(a, b, 0xFBFB);
    const u32 cd = prmt(c, d, 0xFBFB);
    return prmt(ab, cd, 0x5410);
}
DI u32 dp4a(u32 a, u32 b, u32 c) {
    u32 d;
    asm("dp4a.u32.u32 %0, %1, %2, %3;" : "=r"(d) : "r"(a), "r"(b), "r"(c));
    return d;
}

// weight source: true -> constant bank, false -> global staging buffer
template <bool C>
struct Src {
    DI float w(int i)  const { return C ? cBuf.all[i] : gBuf.all[i]; }
    DI u64  wq(int i)  const { return C ? cBuf.pk2[i] : gBuf.pk2[i]; }
};

// staging gather: 5 arrays -> gBuf (scalar view + compact packed view)
__global__ void gather_weights(const float* __restrict__ W1,
                               const float* __restrict__ b1,
                               const float* __restrict__ W2,
                               const float* __restrict__ b2,
                               const float* __restrict__ W3) {
    const int t = threadIdx.x;
    if (t < 68) {
        float v;
        if (t < 16)       v = W1[t];
        else if (t < 24)  v = b1[t - 16];
        else if (t < 56)  v = W2[t - 24];
        else if (t < 60)  v = b2[t - 56];
        else              v = W3[t - 60];
        gBuf.all[t] = v;
    }
    if (t < 30) {
        float lo, hi;
        if (t < 4)        { lo = W1[4 * t];      hi = W1[4 * t + 2]; }
        else if (t < 8)   { const int k = t - 4;  lo = W1[4 * k + 1]; hi = W1[4 * k + 3]; }
        else if (t < 12)  { const int k = t - 8;  lo = b1[2 * k];     hi = b1[2 * k + 1]; }
        else if (t < 28)  { const int e = t - 12; const int a = e >> 3, i = e & 7;
                            lo = W2[16 * a + i];  hi = W2[16 * a + 8 + i]; }
        else              { const int a = t - 28; lo = b2[2 * a];     hi = b2[2 * a + 1]; }
        gBuf.pk2[t] = pack2(lo, hi);
    }
}

template <bool C>
__global__ void __launch_bounds__(128, 6) toy_force_kernel(
    const float4* __restrict__ pos,
    float4*       __restrict__ out,
    int npairs)
{
    __shared__ float u_s[16][8];   // u(m2)_i = sum_{j act} (-v3_j) W2[j][i]
    __shared__ u64 tlo[256];       // force of m1[0:4] given m2
    __shared__ u64 thi[256];       // force of m1[4:8] given m2

    Src<C> S;
    const int tid = threadIdx.x;

    // ---- u table: one (m2, i) per thread ----
    {
        const int i = tid & 7, m = tid >> 3;
        float s = 0.f;
#pragma unroll
        for (int j = 0; j < 4; j++) {
            const float v3n = -(S.w(60 + j) + S.w(64 + j));   // fold -grad
            if (!((m >> j) & 1)) s += v3n * S.w(24 + 8 * j + i);
        }
        u_s[m][i] = s;
    }
    __syncthreads();

    // ---- split force tables: 512 entries ----
    for (int e = tid; e < 512; e += blockDim.x) {
        const bool hi = e >= 256;
        const int ent = e & 255;
        const int m1h = ent & 15, m2 = ent >> 4;
        const int base = hi ? 4 : 0;
        float fx = 0.f, fy = 0.f;
#pragma unroll
        for (int k = 0; k < 4; k++) {
            const int i = base + k;
            const float msk = ((m1h >> k) & 1) ? 0.f : 1.f;
            const float ui = msk * u_s[m2][i];
            fx = fmaf(ui, S.w(2 * i), fx);
            fy = fmaf(ui, S.w(2 * i + 1), fy);
        }
        (hi ? thi : tlo)[ent] = pack2(fx, fy);
    }
    __syncthreads();

    // ---- hoist compact packed weights into registers (30 u64 = 60 regs) ----
    u64 W1px[4], W1py[4], B1p[4], W2p[2][8], B2p[2];
#pragma unroll
    for (int k = 0; k < 4; k++) {
        W1px[k] = S.wq(k);
        W1py[k] = S.wq(4 + k);
        B1p[k]  = S.wq(8 + k);
    }
#pragma unroll
    for (int a = 0; a < 2; a++) {
#pragma unroll
        for (int i = 0; i < 8; i++) W2p[a][i] = S.wq(12 + 8 * a + i);
        B2p[a] = S.wq(28 + a);
    }

    const char* tl = (const char*)tlo;
    const char* th = (const char*)thi;
    const u32 K1 = 0x40201008u;   // byte weights 8,16,32,64 (m1 bits * 8B)
    const u32 K2 = 0x08040201u;   // byte weights 1,2,4,8    (m2 value)
    const u32 ONES = 0x01010101u;

    // one 2-D position -> packed force (f32x2)
    auto evalPos = [&](float x, float y) -> u64 {
        const u64 X = dup2(x), Y = dup2(y);
        u32 z[8];
#pragma unroll
        for (int k = 0; k < 4; k++) {
            const u64 zp = fma2(W1px[k], X, fma2(W1py[k], Y, B1p[k]));
            unpack2(zp, z[2 * k], z[2 * k + 1]);
        }
        u64 HD[8];
#pragma unroll
        for (int i = 0; i < 8; i++)
            HD[i] = dup2(fmaxf(__uint_as_float(z[i]), 0.f));
        u32 z2v[4];
#pragma unroll
        for (int a = 0; a < 2; a++) {
            u64 acc0 = fma2(W2p[a][0], HD[0], B2p[a]);
            acc0 = fma2(W2p[a][1], HD[1], acc0);
            acc0 = fma2(W2p[a][2], HD[2], acc0);
            acc0 = fma2(W2p[a][3], HD[3], acc0);
            u64 acc1 = mul2(W2p[a][4], HD[4]);
            acc1 = fma2(W2p[a][5], HD[5], acc1);
            acc1 = fma2(W2p[a][6], HD[6], acc1);
            acc1 = fma2(W2p[a][7], HD[7], acc1);
            unpack2(add2(acc0, acc1), z2v[2 * a], z2v[2 * a + 1]);
        }
        const u32 d1a = dp4a(sgn4(z[0], z[1], z[2], z[3]) & K1, ONES, 0);
        const u32 d1b = dp4a(sgn4(z[4], z[5], z[6], z[7]) & K1, ONES, 0);
        const u32 m2s = dp4a(sgn4(z2v[0], z2v[1], z2v[2], z2v[3]) & K2, ONES, 0) << 7;
        return add2(*(const u64*)(tl + (d1a + m2s)),
                    *(const u64*)(th + (d1b + m2s)));
    };

    const int stride = gridDim.x * blockDim.x;

    // ---- grid-stride, 2 float4 streams, rotating double prefetch ----
    int ka = blockIdx.x * blockDim.x + tid;
    if (ka >= npairs) return;
    int kb = ka + stride;
    bool hb = kb < npairs;

    float4 pa = pos[ka];
    float4 pb = hb ? pos[kb] : pa;

    for (;;) {
        const int kan = ka + 2 * stride;
        const int kbn = kb + 2 * stride;
        const bool han = kan < npairs;
        const bool hbn = hb && (kbn < npairs);
        float4 na, nb;
        if (han) na = pos[kan];
        if (hbn) nb = pos[kbn];

        {
            const u64 F0 = evalPos(pa.x, pa.y);
            const u64 F1 = evalPos(pa.z, pa.w);
            *(ulonglong2*)&out[ka] = make_ulonglong2(F0, F1);
        }
        if (hb) {
            const u64 G0 = evalPos(pb.x, pb.y);
            const u64 G1 = evalPos(pb.z, pb.w);
            *(ulonglong2*)&out[kb] = make_ulonglong2(G0, G1);
        }

        if (!han) break;
        pa = na;
        pb = hbn ? nb : na;
        ka = kan;
        kb = kbn;
        hb = hbn;
    }
}

extern "C" void kernel_launch(void* const* d_in, const int* in_sizes, int n_in,
                              void* d_out, int out_size) {
    const float* pos = (const float*)d_in[0];
    const float* W1  = (const float*)d_in[1];
    const float* b1  = (const float*)d_in[2];
    const float* W2  = (const float*)d_in[3];
    const float* b2  = (const float*)d_in[4];
    const float* W3  = (const float*)d_in[5];
    float* out = (float*)d_out;

    const int npairs = in_sizes[0] / 4;   // one float4 = 2 positions

    gather_weights<<<1, 128>>>(W1, b1, W2, b2, W3);

    void* gptr = nullptr;
    bool ok = cudaGetSymbolAddress(&gptr, gBuf) == cudaSuccess;
    if (ok)
        ok = cudaMemcpyToSymbolAsync(cBuf, gptr, sizeof(CBuf), 0,
                                     cudaMemcpyDeviceToDevice, 0) == cudaSuccess;

    const int threads = 128;
    const int blocks  = 888;              // 148 SMs x 6 CTAs
    if (ok) {
        toy_force_kernel<true><<<blocks, threads>>>(
            (const float4*)pos, (float4*)out, npairs);
    } else {
        toy_force_kernel<false><<<blocks, threads>>>(
            (const float4*)pos, (float4*)out, npairs);
    }
}

// round 11
// speedup vs baseline: 1.6514x; 1.1252x over previous
#include <cuda_runtime.h>

typedef unsigned long long u64;
typedef unsigned u32;
#define DI __device__ __forceinline__

// ---------- packed f32x2 helpers (PTX-only on sm_103a) ----------
DI u64 pack2(float lo, float hi) {
    u64 r;
    asm("mov.b64 %0, {%1, %2};"
        : "=l"(r) : "r"(__float_as_uint(lo)), "r"(__float_as_uint(hi)));
    return r;
}
DI u64 dup2(float v) {
    u64 r;
    asm("mov.b64 %0, {%1, %1};" : "=l"(r) : "r"(__float_as_uint(v)));
    return r;
}
DI void unpack2(u64 v, u32& lo, u32& hi) {
    asm("mov.b64 {%0, %1}, %2;" : "=r"(lo), "=r"(hi) : "l"(v));
}
DI u64 fma2(u64 a, u64 b, u64 c) {
    u64 d;
    asm("fma.rn.f32x2 %0, %1, %2, %3;" : "=l"(d) : "l"(a), "l"(b), "l"(c));
    return d;
}
DI u64 mul2(u64 a, u64 b) {
    u64 d;
    asm("mul.rn.f32x2 %0, %1, %2;" : "=l"(d) : "l"(a), "l"(b));
    return d;
}
DI u64 add2(u64 a, u64 b) {
    u64 d;
    asm("add.rn.f32x2 %0, %1, %2;" : "=l"(d) : "l"(a), "l"(b));
    return d;
}
DI u32 prmt(u32 a, u32 b, u32 sel) {
    u32 d;
    asm("prmt.b32 %0, %1, %2, %3;" : "=r"(d) : "r"(a), "r"(b), "r"(sel));
    return d;
}
// sign bytes of 4 floats -> [sA,sB,sC,sD] (0xFF where negative)
DI u32 sgn4(u32 a, u32 b, u32 c, u32 d) {
    const u32 ab = prmt(a, b, 0xFBFB);
    const u32 cd = prmt(c, d, 0xFBFB);
    return prmt(ab, cd, 0x5410);
}
DI u32 dp4a(u32 a, u32 b, u32 c) {
    u32 d;
    asm("dp4a.u32.u32 %0, %1, %2, %3;" : "=r"(d) : "r"(a), "r"(b), "r"(c));
    return d;
}

__global__ void __launch_bounds__(128, 6) toy_force_kernel(
    const float4* __restrict__ pos,
    const float*  __restrict__ W1,   // [8,2]
    const float*  __restrict__ b1,   // [8]
    const float*  __restrict__ W2,   // [4,8]
    const float*  __restrict__ b2,   // [4]
    const float*  __restrict__ W3,   // [2,4]
    float4*       __restrict__ out,
    int npairs)
{
    __shared__ float u_s[16][8];   // u(m2)_i = sum_{j act} (-v3_j) W2[j][i]
    __shared__ u64 tlo[256];       // force of m1[0:4] given m2
    __shared__ u64 thi[256];       // force of m1[4:8] given m2

    const int tid = threadIdx.x;

    // ---- u table: one (m2, i) per thread ----
    {
        const int i = tid & 7, m = tid >> 3;
        float s = 0.f;
#pragma unroll
        for (int j = 0; j < 4; j++) {
            const float v3n = -(__ldg(&W3[j]) + __ldg(&W3[4 + j]));  // fold -grad
            if (!((m >> j) & 1)) s += v3n * __ldg(&W2[8 * j + i]);
        }
        u_s[m][i] = s;
    }
    __syncthreads();

    // ---- split force tables: 512 entries ----
    for (int e = tid; e < 512; e += blockDim.x) {
        const bool hi = e >= 256;
        const int ent = e & 255;
        const int m1h = ent & 15, m2 = ent >> 4;
        const int base = hi ? 4 : 0;
        float fx = 0.f, fy = 0.f;
#pragma unroll
        for (int k = 0; k < 4; k++) {
            const int i = base + k;
            const float msk = ((m1h >> k) & 1) ? 0.f : 1.f;
            const float ui = msk * u_s[m2][i];
            fx = fmaf(ui, __ldg(&W1[2 * i]), fx);
            fy = fmaf(ui, __ldg(&W1[2 * i + 1]), fy);
        }
        (hi ? thi : tlo)[ent] = pack2(fx, fy);
    }
    __syncthreads();

    // ---- hoist compact packed weights into registers (30 u64 = 60 regs) ----
    // neuron-pair packing: lane = neuron parity
    u64 W1px[4], W1py[4], B1p[4], W2p[2][8], B2p[2];
#pragma unroll
    for (int k = 0; k < 4; k++) {
        W1px[k] = pack2(__ldg(&W1[4 * k]),     __ldg(&W1[4 * k + 2]));
        W1py[k] = pack2(__ldg(&W1[4 * k + 1]), __ldg(&W1[4 * k + 3]));
        B1p[k]  = pack2(__ldg(&b1[2 * k]),     __ldg(&b1[2 * k + 1]));
    }
#pragma unroll
    for (int a = 0; a < 2; a++) {
#pragma unroll
        for (int i = 0; i < 8; i++)
            W2p[a][i] = pack2(__ldg(&W2[16 * a + i]), __ldg(&W2[16 * a + 8 + i]));
        B2p[a] = pack2(__ldg(&b2[2 * a]), __ldg(&b2[2 * a + 1]));
    }

    const char* tl = (const char*)tlo;
    const char* th = (const char*)thi;
    const u32 K1 = 0x40201008u;   // byte weights 8,16,32,64 (m1 bits * 8B)
    const u32 K2 = 0x08040201u;   // byte weights 1,2,4,8    (m2 value)
    const u32 ONES = 0x01010101u;

    // one 2-D position -> packed force (f32x2)
    auto evalPos = [&](float x, float y) -> u64 {
        const u64 X = dup2(x), Y = dup2(y);
        u32 z[8];
#pragma unroll
        for (int k = 0; k < 4; k++) {
            const u64 zp = fma2(W1px[k], X, fma2(W1py[k], Y, B1p[k]));
            unpack2(zp, z[2 * k], z[2 * k + 1]);
        }
        u64 HD[8];
#pragma unroll
        for (int i = 0; i < 8; i++)
            HD[i] = dup2(fmaxf(__uint_as_float(z[i]), 0.f));
        u32 z2v[4];
#pragma unroll
        for (int a = 0; a < 2; a++) {
            u64 acc0 = fma2(W2p[a][0], HD[0], B2p[a]);
            acc0 = fma2(W2p[a][1], HD[1], acc0);
            acc0 = fma2(W2p[a][2], HD[2], acc0);
            acc0 = fma2(W2p[a][3], HD[3], acc0);
            u64 acc1 = mul2(W2p[a][4], HD[4]);
            acc1 = fma2(W2p[a][5], HD[5], acc1);
            acc1 = fma2(W2p[a][6], HD[6], acc1);
            acc1 = fma2(W2p[a][7], HD[7], acc1);
            unpack2(add2(acc0, acc1), z2v[2 * a], z2v[2 * a + 1]);
        }
        const u32 d1a = dp4a(sgn4(z[0], z[1], z[2], z[3]) & K1, ONES, 0);
        const u32 d1b = dp4a(sgn4(z[4], z[5], z[6], z[7]) & K1, ONES, 0);
        const u32 m2s = dp4a(sgn4(z2v[0], z2v[1], z2v[2], z2v[3]) & K2, ONES, 0) << 7;
        return add2(*(const u64*)(tl + (d1a + m2s)),
                    *(const u64*)(th + (d1b + m2s)));
    };

    const int stride = gridDim.x * blockDim.x;

    // ---- grid-stride, 2 float4 streams, rotating double prefetch ----
    int ka = blockIdx.x * blockDim.x + tid;
    if (ka >= npairs) return;
    int kb = ka + stride;
    bool hb = kb < npairs;

    float4 pa = pos[ka];
    float4 pb = hb ? pos[kb] : pa;

    for (;;) {
        const int kan = ka + 2 * stride;
        const int kbn = kb + 2 * stride;
        const bool han = kan < npairs;
        const bool hbn = hb && (kbn < npairs);
        float4 na, nb;
        if (han) na = pos[kan];
        if (hbn) nb = pos[kbn];

        {
            const u64 F0 = evalPos(pa.x, pa.y);
            const u64 F1 = evalPos(pa.z, pa.w);
            *(ulonglong2*)&out[ka] = make_ulonglong2(F0, F1);
        }
        if (hb) {
            const u64 G0 = evalPos(pb.x, pb.y);
            const u64 G1 = evalPos(pb.z, pb.w);
            *(ulonglong2*)&out[kb] = make_ulonglong2(G0, G1);
        }

        if (!han) break;
        pa = na;
        pb = hbn ? nb : na;
        ka = kan;
        kb = kbn;
        hb = hbn;
    }
}

extern "C" void kernel_launch(void* const* d_in, const int* in_sizes, int n_in,
                              void* d_out, int out_size) {
    const float* pos = (const float*)d_in[0];
    const float* W1  = (const float*)d_in[1];
    const float* b1  = (const float*)d_in[2];
    const float* W2  = (const float*)d_in[3];
    const float* b2  = (const float*)d_in[4];
    const float* W3  = (const float*)d_in[5];
    float* out = (float*)d_out;

    const int npairs = in_sizes[0] / 4;   // one float4 = 2 positions

    const int threads = 128;
    const int blocks  = 888;              // 148 SMs x 6 CTAs
    toy_force_kernel<<<blocks, threads>>>(
        (const float4*)pos, W1, b1, W2, b2, W3, (float4*)out, npairs);
}